// round 11
// baseline (speedup 1.0000x reference)
#include <cuda_runtime.h>
#include <cuda_bf16.h>

// ColorQuantizer: out = PALETTE[argmin_p ||MLP(x) - pal_p||]
// (stop_gradient(hard - soft) + soft == hard numerically; softmax/sqrt are
//  monotone so argmax(weights) == argmin(distance) == argmax(dot - 0.5*|pal|^2))
//
// Inputs (metadata order): x[32,3,512,512] f32, W1[3,32], b1[32], W2[32,3], b2[3]
// Output: [32,3,512,512] f32
//
// R11: relu(t) = (t+|t|)/2 exactly =>
//   processed = [b2 + 0.5(Cx+e)] + sum_j |t_j| * (0.5 u_j),
//   C = sum_j u_j w_j^T (3x3), e = sum_j b1_j u_j, precomputed in prologue.
// Inner loop is pure FFMA2 + one packed-abs AND: no FMNMX, no pack/unpack.

typedef unsigned long long u64;

#define B_DIM  32
#define HW     262144          // 512*512
#define TPB    256
#define VEC    2               // float4 slots per channel per thread (8 px)
#define GRIDX  (HW / 4 / (TPB * VEC))   // 65536 / 512 = 128

#define ABSMASK 0x7fffffff7fffffffULL

__device__ __forceinline__ u64 pk2(float lo, float hi) {
    u64 d; asm("mov.b64 %0, {%1, %2};" : "=l"(d) : "f"(lo), "f"(hi)); return d;
}
__device__ __forceinline__ void up2(float& lo, float& hi, u64 d) {
    asm("mov.b64 {%0, %1}, %2;" : "=f"(lo), "=f"(hi) : "l"(d));
}
__device__ __forceinline__ u64 ffma2(u64 a, u64 b, u64 c) {
    u64 d; asm("fma.rn.f32x2 %0, %1, %2, %3;" : "=l"(d) : "l"(a), "l"(b), "l"(c));
    return d;
}

__global__ __launch_bounds__(TPB, 3) void color_quant_kernel(
    const float* __restrict__ x,
    const float* __restrict__ W1,   // [3][32] row-major
    const float* __restrict__ b1,   // [32]
    const float* __restrict__ W2,   // [32][3] row-major
    const float* __restrict__ b2,   // [3]
    float* __restrict__ out)
{
    // Shared: all values pre-duplicated into both halves of f32x2 lanes.
    // sW1[j]  = {w0,w0, w1,w1, w2,w2, b1,b1}
    // sW2[j]  = {u0',u0', u1',u1', u2',u2', 0,0}   u' = 0.5*u
    // sPal[p] = {px,px, py,py, pz,pz, c,c},  c = -0.5*|pal_p|^2
    // sLin    = 12 duplicated pairs: {C'00,C'01,C'02,D0, C'10..D1, C'20..D2}
    __shared__ __align__(16) float sW1[32 * 8];
    __shared__ __align__(16) float sW2[32 * 8];
    __shared__ __align__(16) float sPal[16 * 8];
    __shared__ __align__(16) float sLin[12 * 2];
    __shared__ float sGat[48];      // palette gather table [16][3]

    const int tid = threadIdx.x;

    if (tid < 32) {
        const int j = tid;
        float w0 = W1[j], w1 = W1[32 + j], w2 = W1[64 + j], bb = b1[j];
        float4* v = (float4*)(sW1 + j * 8);
        v[0] = make_float4(w0, w0, w1, w1);
        v[1] = make_float4(w2, w2, bb, bb);
        // u' = 0.5 * u  (exact power-of-2 scale)
        float u0 = 0.5f * W2[3 * j];
        float u1 = 0.5f * W2[3 * j + 1];
        float u2 = 0.5f * W2[3 * j + 2];
        float4* q = (float4*)(sW2 + j * 8);
        q[0] = make_float4(u0, u0, u1, u1);
        q[1] = make_float4(u2, u2, 0.f, 0.f);
    }
    if (tid < 16) {
        // pal = (c/255)*2 - 1, each op round-to-nearest fp32 (matches numpy)
        const float C[16][3] = {
            {0,0,0},{255,255,255},{255,0,0},{0,255,0},{0,0,255},{255,255,0},
            {255,0,255},{0,255,255},{128,128,128},{128,0,0},{0,128,0},{0,0,128},
            {128,128,0},{128,0,128},{0,128,128},{192,192,192}};
        float px = __fsub_rn(__fmul_rn(__fdiv_rn(C[tid][0], 255.0f), 2.0f), 1.0f);
        float py = __fsub_rn(__fmul_rn(__fdiv_rn(C[tid][1], 255.0f), 2.0f), 1.0f);
        float pz = __fsub_rn(__fmul_rn(__fdiv_rn(C[tid][2], 255.0f), 2.0f), 1.0f);
        float n  = __fmaf_rn(pz, pz, __fmaf_rn(py, py, __fmul_rn(px, px)));
        float cc = -0.5f * n;
        float4* t = (float4*)(sPal + tid * 8);
        t[0] = make_float4(px, px, py, py);
        t[1] = make_float4(pz, pz, cc, cc);
        sGat[tid * 3 + 0] = px;
        sGat[tid * 3 + 1] = py;
        sGat[tid * 3 + 2] = pz;
    }
    // C'[i][k] = 0.5 * sum_j W2[j][i] * W1[k][j]   (i = out ch, k = in ch)
    if (tid >= 32 && tid < 41) {
        int i = (tid - 32) / 3, k = (tid - 32) % 3;
        float s = 0.f;
        #pragma unroll 8
        for (int j = 0; j < 32; j++)
            s = __fmaf_rn(W2[3 * j + i], W1[32 * k + j], s);
        s *= 0.5f;
        int l = i * 4 + k;              // slot within sLin (row-major, D at col 3)
        sLin[2 * l] = s; sLin[2 * l + 1] = s;
    }
    // D[i] = b2[i] + 0.5 * sum_j b1[j] * W2[j][i]
    if (tid >= 48 && tid < 51) {
        int i = tid - 48;
        float s = 0.f;
        #pragma unroll 8
        for (int j = 0; j < 32; j++)
            s = __fmaf_rn(b1[j], W2[3 * j + i], s);
        s = __fmaf_rn(0.5f, s, b2[i]);
        int l = i * 4 + 3;
        sLin[2 * l] = s; sLin[2 * l + 1] = s;
    }
    __syncthreads();

    const float* xb = x   + (size_t)blockIdx.y * (3 * HW);
    float*       ob = out + (size_t)blockIdx.y * (3 * HW);
    const int it0 = blockIdx.x * (TPB * VEC) + tid;
    const int r0 = it0 * 4;             // first float4 (floats)
    const int r1 = (it0 + TPB) * 4;     // second float4

    const ulonglong2* w1v = (const ulonglong2*)sW1;
    const ulonglong2* w2v = (const ulonglong2*)sW2;
    const ulonglong2* pv  = (const ulonglong2*)sPal;
    const u64*        lv  = (const u64*)sLin;   // 12 duplicated pairs

    // Load 8 pixels: 2 coalesced float4 per channel (6x LDG.128, max MLP)
    float4 c0a = *(const float4*)(xb + r0);
    float4 c0b = *(const float4*)(xb + r1);
    float4 c1a = *(const float4*)(xb + HW + r0);
    float4 c1b = *(const float4*)(xb + HW + r1);
    float4 c2a = *(const float4*)(xb + 2 * HW + r0);
    float4 c2b = *(const float4*)(xb + 2 * HW + r1);

    u64 X0[4], X1[4], X2[4];
    X0[0] = pk2(c0a.x, c0a.y); X0[1] = pk2(c0a.z, c0a.w);
    X0[2] = pk2(c0b.x, c0b.y); X0[3] = pk2(c0b.z, c0b.w);
    X1[0] = pk2(c1a.x, c1a.y); X1[1] = pk2(c1a.z, c1a.w);
    X1[2] = pk2(c1b.x, c1b.y); X1[3] = pk2(c1b.z, c1b.w);
    X2[0] = pk2(c2a.x, c2a.y); X2[1] = pk2(c2a.z, c2a.w);
    X2[2] = pk2(c2b.x, c2b.y); X2[3] = pk2(c2b.z, c2b.w);

    // A init = C' x + D  (linear half of the relu identity)
    u64 A0[4], A1[4], A2[4];
    {
        u64 L00 = lv[0], L01 = lv[1], L02 = lv[2],  D0 = lv[3];
        u64 L10 = lv[4], L11 = lv[5], L12 = lv[6],  D1 = lv[7];
        u64 L20 = lv[8], L21 = lv[9], L22 = lv[10], D2 = lv[11];
        #pragma unroll
        for (int q = 0; q < 4; q++) {
            u64 t;
            t = ffma2(X2[q], L02, D0); t = ffma2(X1[q], L01, t); A0[q] = ffma2(X0[q], L00, t);
            t = ffma2(X2[q], L12, D1); t = ffma2(X1[q], L11, t); A1[q] = ffma2(X0[q], L10, t);
            t = ffma2(X2[q], L22, D2); t = ffma2(X1[q], L21, t); A2[q] = ffma2(X0[q], L20, t);
        }
    }

    // A += sum_j |t_j| * u'_j ; pure FFMA2 + packed abs (one 64-bit AND)
    #pragma unroll 4
    for (int j = 0; j < 32; j++) {
        ulonglong2 Wa = w1v[2 * j];       // {w0w0, w1w1}
        ulonglong2 Wb = w1v[2 * j + 1];   // {w2w2, bb}
        ulonglong2 Ua = w2v[2 * j];       // {u0'u0', u1'u1'}
        ulonglong2 Ub = w2v[2 * j + 1];   // {u2'u2', 0}
        u64 h[4];
        #pragma unroll
        for (int q = 0; q < 4; q++) {
            u64 t = ffma2(X0[q], Wa.x, Wb.y);
            t = ffma2(X1[q], Wa.y, t);
            t = ffma2(X2[q], Wb.x, t);
            h[q] = t & ABSMASK;           // packed |t| (exact)
        }
        #pragma unroll
        for (int q = 0; q < 4; q++) {
            A0[q] = ffma2(h[q], Ua.x, A0[q]);
            A1[q] = ffma2(h[q], Ua.y, A1[q]);
            A2[q] = ffma2(h[q], Ub.x, A2[q]);
        }
    }

    // argmax_p of (proc . pal_p - 0.5*|pal_p|^2); strict > keeps first index
    float bs[8];
    int   id[8];
    {
        ulonglong2 Pa = pv[0], Pb = pv[1];
        #pragma unroll
        for (int q = 0; q < 4; q++) {
            u64 t = ffma2(A0[q], Pa.x, Pb.y);
            t = ffma2(A1[q], Pa.y, t);
            t = ffma2(A2[q], Pb.x, t);
            up2(bs[2 * q], bs[2 * q + 1], t);
            id[2 * q] = 0; id[2 * q + 1] = 0;
        }
    }
    #pragma unroll 5
    for (int p = 1; p < 16; p++) {
        ulonglong2 Pa = pv[2 * p], Pb = pv[2 * p + 1];
        #pragma unroll
        for (int q = 0; q < 4; q++) {
            u64 t = ffma2(A0[q], Pa.x, Pb.y);
            t = ffma2(A1[q], Pa.y, t);
            t = ffma2(A2[q], Pb.x, t);
            float t0, t1; up2(t0, t1, t);
            if (t0 > bs[2 * q])     { bs[2 * q] = t0;     id[2 * q] = p; }
            if (t1 > bs[2 * q + 1]) { bs[2 * q + 1] = t1; id[2 * q + 1] = p; }
        }
    }

    // gather hard-quantized colors, store 2 coalesced STG.128 per channel
    float4 o;
    o = make_float4(sGat[id[0] * 3 + 0], sGat[id[1] * 3 + 0],
                    sGat[id[2] * 3 + 0], sGat[id[3] * 3 + 0]);
    *(float4*)(ob + r0) = o;
    o = make_float4(sGat[id[4] * 3 + 0], sGat[id[5] * 3 + 0],
                    sGat[id[6] * 3 + 0], sGat[id[7] * 3 + 0]);
    *(float4*)(ob + r1) = o;

    o = make_float4(sGat[id[0] * 3 + 1], sGat[id[1] * 3 + 1],
                    sGat[id[2] * 3 + 1], sGat[id[3] * 3 + 1]);
    *(float4*)(ob + HW + r0) = o;
    o = make_float4(sGat[id[4] * 3 + 1], sGat[id[5] * 3 + 1],
                    sGat[id[6] * 3 + 1], sGat[id[7] * 3 + 1]);
    *(float4*)(ob + HW + r1) = o;

    o = make_float4(sGat[id[0] * 3 + 2], sGat[id[1] * 3 + 2],
                    sGat[id[2] * 3 + 2], sGat[id[3] * 3 + 2]);
    *(float4*)(ob + 2 * HW + r0) = o;
    o = make_float4(sGat[id[4] * 3 + 2], sGat[id[5] * 3 + 2],
                    sGat[id[6] * 3 + 2], sGat[id[7] * 3 + 2]);
    *(float4*)(ob + 2 * HW + r1) = o;
}

extern "C" void kernel_launch(void* const* d_in, const int* in_sizes, int n_in,
                              void* d_out, int out_size) {
    const float* x  = (const float*)d_in[0];
    const float* W1 = (const float*)d_in[1];
    const float* b1 = (const float*)d_in[2];
    const float* W2 = (const float*)d_in[3];
    const float* b2 = (const float*)d_in[4];
    float* out = (float*)d_out;

    dim3 grid(GRIDX, B_DIM);   // 128 x 32 = 4096 CTAs, 8 px/thread
    dim3 block(TPB);
    color_quant_kernel<<<grid, block>>>(x, W1, b1, W2, b2, out);
}

// round 16
// speedup vs baseline: 1.1348x; 1.1348x over previous
#include <cuda_runtime.h>
#include <cuda_bf16.h>

// ColorQuantizer: out = PALETTE[argmin_p ||MLP(x) - pal_p||]
// (stop_gradient(hard - soft) + soft == hard numerically; softmax/sqrt are
//  monotone so argmax(weights) == argmin(distance) == argmax(dot - 0.5*|pal|^2))
//
// Inputs (metadata order): x[32,3,512,512] f32, W1[3,32], b1[32], W2[32,3], b2[3]
// Output: [32,3,512,512] f32
//
// Identical arithmetic to the 115us kernel (8 px/thread, FFMA2 + FMNMX relu),
// but all FFMA2 groups are WEIGHT-MAJOR staged: consecutive instructions share
// the weight operand so the operand-reuse cache drops RF bank reads from 3+3
// to 2+2 (FFMA2 rt 3 -> 2). Dependency spacing of 4 instrs covers FMA latency.

typedef unsigned long long u64;

#define B_DIM  32
#define HW     262144          // 512*512
#define TPB    256
#define VEC    2               // float4 slots per channel per thread (8 px)
#define GRIDX  (HW / 4 / (TPB * VEC))   // 65536 / 512 = 128

__device__ __forceinline__ u64 pk2(float lo, float hi) {
    u64 d; asm("mov.b64 %0, {%1, %2};" : "=l"(d) : "f"(lo), "f"(hi)); return d;
}
__device__ __forceinline__ void up2(float& lo, float& hi, u64 d) {
    asm("mov.b64 {%0, %1}, %2;" : "=f"(lo), "=f"(hi) : "l"(d));
}
__device__ __forceinline__ u64 ffma2(u64 a, u64 b, u64 c) {
    u64 d; asm("fma.rn.f32x2 %0, %1, %2, %3;" : "=l"(d) : "l"(a), "l"(b), "l"(c));
    return d;
}

__global__ __launch_bounds__(TPB, 3) void color_quant_kernel(
    const float* __restrict__ x,
    const float* __restrict__ W1,   // [3][32] row-major
    const float* __restrict__ b1,   // [32]
    const float* __restrict__ W2,   // [32][3] row-major
    const float* __restrict__ b2,   // [3]
    float* __restrict__ out)
{
    // Shared: weights pre-duplicated into both halves of f32x2 lanes.
    // sW1[j]  = {w0,w0, w1,w1, w2,w2, b1,b1}        (2x LDS.128)
    // sW2[j]  = {u0,u0, u1,u1, u2,u2, 0,0}
    // sPal[p] = {px,px, py,py, pz,pz, c,c},  c = -0.5*|pal_p|^2
    __shared__ __align__(16) float sW1[32 * 8];
    __shared__ __align__(16) float sW2[32 * 8];
    __shared__ __align__(16) float sPal[16 * 8];
    __shared__ float sGat[48];      // palette gather table [16][3]

    const int tid = threadIdx.x;

    if (tid < 32) {
        const int j = tid;
        float w0 = W1[j], w1 = W1[32 + j], w2 = W1[64 + j], bb = b1[j];
        float4* v = (float4*)(sW1 + j * 8);
        v[0] = make_float4(w0, w0, w1, w1);
        v[1] = make_float4(w2, w2, bb, bb);
        float u0 = W2[3 * j], u1 = W2[3 * j + 1], u2 = W2[3 * j + 2];
        float4* q = (float4*)(sW2 + j * 8);
        q[0] = make_float4(u0, u0, u1, u1);
        q[1] = make_float4(u2, u2, 0.f, 0.f);
    }
    if (tid < 16) {
        // pal = (c/255)*2 - 1, each op round-to-nearest fp32 (matches numpy)
        const float C[16][3] = {
            {0,0,0},{255,255,255},{255,0,0},{0,255,0},{0,0,255},{255,255,0},
            {255,0,255},{0,255,255},{128,128,128},{128,0,0},{0,128,0},{0,0,128},
            {128,128,0},{128,0,128},{0,128,128},{192,192,192}};
        float px = __fsub_rn(__fmul_rn(__fdiv_rn(C[tid][0], 255.0f), 2.0f), 1.0f);
        float py = __fsub_rn(__fmul_rn(__fdiv_rn(C[tid][1], 255.0f), 2.0f), 1.0f);
        float pz = __fsub_rn(__fmul_rn(__fdiv_rn(C[tid][2], 255.0f), 2.0f), 1.0f);
        float n  = __fmaf_rn(pz, pz, __fmaf_rn(py, py, __fmul_rn(px, px)));
        float cc = -0.5f * n;
        float4* t = (float4*)(sPal + tid * 8);
        t[0] = make_float4(px, px, py, py);
        t[1] = make_float4(pz, pz, cc, cc);
        sGat[tid * 3 + 0] = px;
        sGat[tid * 3 + 1] = py;
        sGat[tid * 3 + 2] = pz;
    }
    __syncthreads();

    const float bz0 = b2[0], bz1 = b2[1], bz2 = b2[2];
    const u64 Bp0 = pk2(bz0, bz0), Bp1 = pk2(bz1, bz1), Bp2 = pk2(bz2, bz2);

    const float* xb = x   + (size_t)blockIdx.y * (3 * HW);
    float*       ob = out + (size_t)blockIdx.y * (3 * HW);
    const int it0 = blockIdx.x * (TPB * VEC) + tid;
    const int r0 = it0 * 4;             // first float4 (floats)
    const int r1 = (it0 + TPB) * 4;     // second float4

    const ulonglong2* w1v = (const ulonglong2*)sW1;
    const ulonglong2* w2v = (const ulonglong2*)sW2;
    const ulonglong2* pv  = (const ulonglong2*)sPal;

    // Load 8 pixels: 2 coalesced float4 per channel (6x LDG.128, max MLP)
    float4 c0a = *(const float4*)(xb + r0);
    float4 c0b = *(const float4*)(xb + r1);
    float4 c1a = *(const float4*)(xb + HW + r0);
    float4 c1b = *(const float4*)(xb + HW + r1);
    float4 c2a = *(const float4*)(xb + 2 * HW + r0);
    float4 c2b = *(const float4*)(xb + 2 * HW + r1);

    u64 X0[4], X1[4], X2[4];
    X0[0] = pk2(c0a.x, c0a.y); X0[1] = pk2(c0a.z, c0a.w);
    X0[2] = pk2(c0b.x, c0b.y); X0[3] = pk2(c0b.z, c0b.w);
    X1[0] = pk2(c1a.x, c1a.y); X1[1] = pk2(c1a.z, c1a.w);
    X1[2] = pk2(c1b.x, c1b.y); X1[3] = pk2(c1b.z, c1b.w);
    X2[0] = pk2(c2a.x, c2a.y); X2[1] = pk2(c2a.z, c2a.w);
    X2[2] = pk2(c2b.x, c2b.y); X2[3] = pk2(c2b.z, c2b.w);

    u64 A0[4], A1[4], A2[4];
    #pragma unroll
    for (int q = 0; q < 4; q++) { A0[q] = Bp0; A1[q] = Bp1; A2[q] = Bp2; }

    // fused layer1 (relu) + layer2 — WEIGHT-MAJOR stages: consecutive FFMA2
    // share the weight operand (reuse cache) and consumers trail producers
    // by 4 instructions.
    #pragma unroll 4
    for (int j = 0; j < 32; j++) {
        ulonglong2 Wa = w1v[2 * j];       // {w0w0, w1w1}
        ulonglong2 Wb = w1v[2 * j + 1];   // {w2w2, bb}
        ulonglong2 Ua = w2v[2 * j];       // {u0u0, u1u1}
        ulonglong2 Ub = w2v[2 * j + 1];   // {u2u2, 0}
        u64 t[4];
        #pragma unroll
        for (int q = 0; q < 4; q++) t[q] = ffma2(X0[q], Wa.x, Wb.y);
        #pragma unroll
        for (int q = 0; q < 4; q++) t[q] = ffma2(X1[q], Wa.y, t[q]);
        #pragma unroll
        for (int q = 0; q < 4; q++) t[q] = ffma2(X2[q], Wb.x, t[q]);
        #pragma unroll
        for (int q = 0; q < 4; q++) {
            float lo, hi;
            up2(lo, hi, t[q]);
            lo = fmaxf(lo, 0.f); hi = fmaxf(hi, 0.f);
            t[q] = pk2(lo, hi);
        }
        #pragma unroll
        for (int q = 0; q < 4; q++) A0[q] = ffma2(t[q], Ua.x, A0[q]);
        #pragma unroll
        for (int q = 0; q < 4; q++) A1[q] = ffma2(t[q], Ua.y, A1[q]);
        #pragma unroll
        for (int q = 0; q < 4; q++) A2[q] = ffma2(t[q], Ub.x, A2[q]);
    }

    // argmax_p of (proc . pal_p - 0.5*|pal_p|^2); strict > keeps first index
    // Stage-major over q: consecutive FFMA2 share the palette operand.
    float bs[8];
    int   id[8];
    {
        ulonglong2 Pa = pv[0], Pb = pv[1];
        u64 s[4];
        #pragma unroll
        for (int q = 0; q < 4; q++) s[q] = ffma2(A0[q], Pa.x, Pb.y);
        #pragma unroll
        for (int q = 0; q < 4; q++) s[q] = ffma2(A1[q], Pa.y, s[q]);
        #pragma unroll
        for (int q = 0; q < 4; q++) s[q] = ffma2(A2[q], Pb.x, s[q]);
        #pragma unroll
        for (int q = 0; q < 4; q++) {
            up2(bs[2 * q], bs[2 * q + 1], s[q]);
            id[2 * q] = 0; id[2 * q + 1] = 0;
        }
    }
    #pragma unroll 5
    for (int p = 1; p < 16; p++) {
        ulonglong2 Pa = pv[2 * p], Pb = pv[2 * p + 1];
        u64 s[4];
        #pragma unroll
        for (int q = 0; q < 4; q++) s[q] = ffma2(A0[q], Pa.x, Pb.y);
        #pragma unroll
        for (int q = 0; q < 4; q++) s[q] = ffma2(A1[q], Pa.y, s[q]);
        #pragma unroll
        for (int q = 0; q < 4; q++) s[q] = ffma2(A2[q], Pb.x, s[q]);
        #pragma unroll
        for (int q = 0; q < 4; q++) {
            float t0, t1; up2(t0, t1, s[q]);
            if (t0 > bs[2 * q])     { bs[2 * q] = t0;     id[2 * q] = p; }
            if (t1 > bs[2 * q + 1]) { bs[2 * q + 1] = t1; id[2 * q + 1] = p; }
        }
    }

    // gather hard-quantized colors, store 2 coalesced STG.128 per channel
    float4 o;
    o = make_float4(sGat[id[0] * 3 + 0], sGat[id[1] * 3 + 0],
                    sGat[id[2] * 3 + 0], sGat[id[3] * 3 + 0]);
    *(float4*)(ob + r0) = o;
    o = make_float4(sGat[id[4] * 3 + 0], sGat[id[5] * 3 + 0],
                    sGat[id[6] * 3 + 0], sGat[id[7] * 3 + 0]);
    *(float4*)(ob + r1) = o;

    o = make_float4(sGat[id[0] * 3 + 1], sGat[id[1] * 3 + 1],
                    sGat[id[2] * 3 + 1], sGat[id[3] * 3 + 1]);
    *(float4*)(ob + HW + r0) = o;
    o = make_float4(sGat[id[4] * 3 + 1], sGat[id[5] * 3 + 1],
                    sGat[id[6] * 3 + 1], sGat[id[7] * 3 + 1]);
    *(float4*)(ob + HW + r1) = o;

    o = make_float4(sGat[id[0] * 3 + 2], sGat[id[1] * 3 + 2],
                    sGat[id[2] * 3 + 2], sGat[id[3] * 3 + 2]);
    *(float4*)(ob + 2 * HW + r0) = o;
    o = make_float4(sGat[id[4] * 3 + 2], sGat[id[5] * 3 + 2],
                    sGat[id[6] * 3 + 2], sGat[id[7] * 3 + 2]);
    *(float4*)(ob + 2 * HW + r1) = o;
}

extern "C" void kernel_launch(void* const* d_in, const int* in_sizes, int n_in,
                              void* d_out, int out_size) {
    const float* x  = (const float*)d_in[0];
    const float* W1 = (const float*)d_in[1];
    const float* b1 = (const float*)d_in[2];
    const float* W2 = (const float*)d_in[3];
    const float* b2 = (const float*)d_in[4];
    float* out = (float*)d_out;

    dim3 grid(GRIDX, B_DIM);   // 128 x 32 = 4096 CTAs, 8 px/thread
    dim3 block(TPB);
    color_quant_kernel<<<grid, block>>>(x, W1, b1, W2, b2, out);
}

// round 17
// speedup vs baseline: 1.3129x; 1.1570x over previous
#include <cuda_runtime.h>
#include <cuda_bf16.h>

// ColorQuantizer: out = PALETTE[argmin_p ||MLP(x) - pal_p||]
// (stop_gradient(hard-soft)+soft == hard numerically; softmax/sqrt monotone
//  => argmax(weights) == argmax(dot(proc,pal_p) - 0.5|pal_p|^2))
//
// Inputs: x[32,3,512,512] f32, W1[3,32], b1[32], W2[32,3], b2[3]
// Output: [32,3,512,512] f32
//
// R17: structured argmax. Palette comps in {-1,+1,g,s}:
//  idx0-7  : max = |A0|+|A1|+|A2| - 1.5, index from sign LUT
//  idx9-11 : (1+g)max3(A) - S + c9 ; idx12-14: g*S - (1+g)min3(A) + c12
//  idx8/15 : fmaf(g|s, S, c)
// Replaces 48 FFMA2 + ~90 alu + 32 palette-LDS per pair with ~20 fma + ~70 alu.
// Mainloop unchanged from the 104.7us weight-major kernel.

typedef unsigned long long u64;

#define B_DIM  32
#define HW     262144          // 512*512
#define TPB    256
#define VEC    2               // float4 slots per channel per thread (8 px)
#define GRIDX  (HW / 4 / (TPB * VEC))   // 65536 / 512 = 128

#define ABSMASK 0x7fffffff7fffffffULL
#define SIGNLUT 0x9D9B9u   // 3-bit palette idx per sign pattern m=(s0|s1<<1|s2<<2)

__device__ __forceinline__ u64 pk2(float lo, float hi) {
    u64 d; asm("mov.b64 %0, {%1, %2};" : "=l"(d) : "f"(lo), "f"(hi)); return d;
}
__device__ __forceinline__ void up2(float& lo, float& hi, u64 d) {
    asm("mov.b64 {%0, %1}, %2;" : "=f"(lo), "=f"(hi) : "l"(d));
}
__device__ __forceinline__ u64 ffma2(u64 a, u64 b, u64 c) {
    u64 d; asm("fma.rn.f32x2 %0, %1, %2, %3;" : "=l"(d) : "l"(a), "l"(b), "l"(c));
    return d;
}
__device__ __forceinline__ u64 fadd2(u64 a, u64 b) {
    u64 d; asm("add.rn.f32x2 %0, %1, %2;" : "=l"(d) : "l"(a), "l"(b));
    return d;
}

// per-pixel structured argmax over the 16 palette scores
__device__ __forceinline__ int pick16(float a0, float a1, float a2,
                                      float Sv, float VAv,
                                      float g, float sC, float G1,
                                      float c8, float c9, float c12, float c15)
{
    // group A (idx 0-7, +-1 corners): |A| sum, index from sign bits
    float best = VAv - 1.5f;
    unsigned m = (__float_as_uint(a0) >> 31)
               | ((__float_as_uint(a1) >> 31) << 1)
               | ((__float_as_uint(a2) >> 31) << 2);
    int idx = (int)((SIGNLUT >> (3u * m)) & 7u);

    // idx 8 (gray g,g,g)
    float v8 = __fmaf_rn(g, Sv, c8);
    if (v8 > best) { best = v8; idx = 8; }

    // idx 9-11 (one comp g, others -1): (1+g)*max3(A) - S + c9
    float mB = a0; int iB = 9;
    if (a1 > mB) { mB = a1; iB = 10; }
    if (a2 > mB) { mB = a2; iB = 11; }
    float vB = __fmaf_rn(G1, mB, c9 - Sv);
    if (vB > best) { best = vB; idx = iB; }

    // idx 12-14 (one comp -1, others g): g*S - (1+g)*min3(A) + c12
    // order: idx12 <-> a2, idx13 <-> a1, idx14 <-> a0 (first-index on ties)
    float mC = a2; int iC = 12;
    if (a1 < mC) { mC = a1; iC = 13; }
    if (a0 < mC) { mC = a0; iC = 14; }
    float vC = __fmaf_rn(-G1, mC, __fmaf_rn(g, Sv, c12));
    if (vC > best) { best = vC; idx = iC; }

    // idx 15 (gray s,s,s)
    float v15 = __fmaf_rn(sC, Sv, c15);
    if (v15 > best) { idx = 15; }
    return idx;
}

__global__ __launch_bounds__(TPB, 3) void color_quant_kernel(
    const float* __restrict__ x,
    const float* __restrict__ W1,   // [3][32] row-major
    const float* __restrict__ b1,   // [32]
    const float* __restrict__ W2,   // [32][3] row-major
    const float* __restrict__ b2,   // [3]
    float* __restrict__ out)
{
    // Shared: weights pre-duplicated into both halves of f32x2 lanes.
    // sW1[j]  = {w0,w0, w1,w1, w2,w2, b1,b1}        (2x LDS.128)
    // sW2[j]  = {u0,u0, u1,u1, u2,u2, 0,0}
    __shared__ __align__(16) float sW1[32 * 8];
    __shared__ __align__(16) float sW2[32 * 8];
    __shared__ float sGat[48];      // palette gather table [16][3]

    const int tid = threadIdx.x;

    if (tid < 32) {
        const int j = tid;
        float w0 = W1[j], w1 = W1[32 + j], w2 = W1[64 + j], bb = b1[j];
        float4* v = (float4*)(sW1 + j * 8);
        v[0] = make_float4(w0, w0, w1, w1);
        v[1] = make_float4(w2, w2, bb, bb);
        float u0 = W2[3 * j], u1 = W2[3 * j + 1], u2 = W2[3 * j + 2];
        float4* q = (float4*)(sW2 + j * 8);
        q[0] = make_float4(u0, u0, u1, u1);
        q[1] = make_float4(u2, u2, 0.f, 0.f);
    }
    if (tid < 16) {
        // pal = (c/255)*2 - 1, each op round-to-nearest fp32 (matches numpy)
        const float C[16][3] = {
            {0,0,0},{255,255,255},{255,0,0},{0,255,0},{0,0,255},{255,255,0},
            {255,0,255},{0,255,255},{128,128,128},{128,0,0},{0,128,0},{0,0,128},
            {128,128,0},{128,0,128},{0,128,128},{192,192,192}};
        float px = __fsub_rn(__fmul_rn(__fdiv_rn(C[tid][0], 255.0f), 2.0f), 1.0f);
        float py = __fsub_rn(__fmul_rn(__fdiv_rn(C[tid][1], 255.0f), 2.0f), 1.0f);
        float pz = __fsub_rn(__fmul_rn(__fdiv_rn(C[tid][2], 255.0f), 2.0f), 1.0f);
        sGat[tid * 3 + 0] = px;
        sGat[tid * 3 + 1] = py;
        sGat[tid * 3 + 2] = pz;
    }
    __syncthreads();

    // structured-argmax constants (compile-time foldable)
    const float g   = __fsub_rn(__fmul_rn(__fdiv_rn(128.0f, 255.0f), 2.0f), 1.0f);
    const float sC  = __fsub_rn(__fmul_rn(__fdiv_rn(192.0f, 255.0f), 2.0f), 1.0f);
    const float G1  = 1.0f + g;
    const float c8  = -1.5f * g * g;
    const float c9  = -0.5f * (g * g + 2.0f);
    const float c12 = -0.5f * (2.0f * g * g + 1.0f);
    const float c15 = -1.5f * sC * sC;

    const float bz0 = b2[0], bz1 = b2[1], bz2 = b2[2];
    const u64 Bp0 = pk2(bz0, bz0), Bp1 = pk2(bz1, bz1), Bp2 = pk2(bz2, bz2);

    const float* xb = x   + (size_t)blockIdx.y * (3 * HW);
    float*       ob = out + (size_t)blockIdx.y * (3 * HW);
    const int it0 = blockIdx.x * (TPB * VEC) + tid;
    const int r0 = it0 * 4;             // first float4 (floats)
    const int r1 = (it0 + TPB) * 4;     // second float4

    const ulonglong2* w1v = (const ulonglong2*)sW1;
    const ulonglong2* w2v = (const ulonglong2*)sW2;

    // Load 8 pixels: 2 coalesced float4 per channel (6x LDG.128, max MLP)
    float4 c0a = *(const float4*)(xb + r0);
    float4 c0b = *(const float4*)(xb + r1);
    float4 c1a = *(const float4*)(xb + HW + r0);
    float4 c1b = *(const float4*)(xb + HW + r1);
    float4 c2a = *(const float4*)(xb + 2 * HW + r0);
    float4 c2b = *(const float4*)(xb + 2 * HW + r1);

    u64 X0[4], X1[4], X2[4];
    X0[0] = pk2(c0a.x, c0a.y); X0[1] = pk2(c0a.z, c0a.w);
    X0[2] = pk2(c0b.x, c0b.y); X0[3] = pk2(c0b.z, c0b.w);
    X1[0] = pk2(c1a.x, c1a.y); X1[1] = pk2(c1a.z, c1a.w);
    X1[2] = pk2(c1b.x, c1b.y); X1[3] = pk2(c1b.z, c1b.w);
    X2[0] = pk2(c2a.x, c2a.y); X2[1] = pk2(c2a.z, c2a.w);
    X2[2] = pk2(c2b.x, c2b.y); X2[3] = pk2(c2b.z, c2b.w);

    u64 A0[4], A1[4], A2[4];
    #pragma unroll
    for (int q = 0; q < 4; q++) { A0[q] = Bp0; A1[q] = Bp1; A2[q] = Bp2; }

    // fused layer1 (relu) + layer2 — WEIGHT-MAJOR stages (operand reuse + ILP)
    #pragma unroll 4
    for (int j = 0; j < 32; j++) {
        ulonglong2 Wa = w1v[2 * j];       // {w0w0, w1w1}
        ulonglong2 Wb = w1v[2 * j + 1];   // {w2w2, bb}
        ulonglong2 Ua = w2v[2 * j];       // {u0u0, u1u1}
        ulonglong2 Ub = w2v[2 * j + 1];   // {u2u2, 0}
        u64 t[4];
        #pragma unroll
        for (int q = 0; q < 4; q++) t[q] = ffma2(X0[q], Wa.x, Wb.y);
        #pragma unroll
        for (int q = 0; q < 4; q++) t[q] = ffma2(X1[q], Wa.y, t[q]);
        #pragma unroll
        for (int q = 0; q < 4; q++) t[q] = ffma2(X2[q], Wb.x, t[q]);
        #pragma unroll
        for (int q = 0; q < 4; q++) {
            float lo, hi;
            up2(lo, hi, t[q]);
            lo = fmaxf(lo, 0.f); hi = fmaxf(hi, 0.f);
            t[q] = pk2(lo, hi);
        }
        #pragma unroll
        for (int q = 0; q < 4; q++) A0[q] = ffma2(t[q], Ua.x, A0[q]);
        #pragma unroll
        for (int q = 0; q < 4; q++) A1[q] = ffma2(t[q], Ua.y, A1[q]);
        #pragma unroll
        for (int q = 0; q < 4; q++) A2[q] = ffma2(t[q], Ub.x, A2[q]);
    }

    // structured argmax per pair
    int id[8];
    #pragma unroll
    for (int q = 0; q < 4; q++) {
        u64 S  = fadd2(fadd2(A0[q], A1[q]), A2[q]);
        u64 VA = fadd2(fadd2(A0[q] & ABSMASK, A1[q] & ABSMASK), A2[q] & ABSMASK);
        float a0l, a0h, a1l, a1h, a2l, a2h, Sl, Sh, Vl, Vh;
        up2(a0l, a0h, A0[q]);
        up2(a1l, a1h, A1[q]);
        up2(a2l, a2h, A2[q]);
        up2(Sl, Sh, S);
        up2(Vl, Vh, VA);
        id[2 * q]     = pick16(a0l, a1l, a2l, Sl, Vl, g, sC, G1, c8, c9, c12, c15);
        id[2 * q + 1] = pick16(a0h, a1h, a2h, Sh, Vh, g, sC, G1, c8, c9, c12, c15);
    }

    // gather hard-quantized colors, store 2 coalesced STG.128 per channel
    float4 o;
    o = make_float4(sGat[id[0] * 3 + 0], sGat[id[1] * 3 + 0],
                    sGat[id[2] * 3 + 0], sGat[id[3] * 3 + 0]);
    *(float4*)(ob + r0) = o;
    o = make_float4(sGat[id[4] * 3 + 0], sGat[id[5] * 3 + 0],
                    sGat[id[6] * 3 + 0], sGat[id[7] * 3 + 0]);
    *(float4*)(ob + r1) = o;

    o = make_float4(sGat[id[0] * 3 + 1], sGat[id[1] * 3 + 1],
                    sGat[id[2] * 3 + 1], sGat[id[3] * 3 + 1]);
    *(float4*)(ob + HW + r0) = o;
    o = make_float4(sGat[id[4] * 3 + 1], sGat[id[5] * 3 + 1],
                    sGat[id[6] * 3 + 1], sGat[id[7] * 3 + 1]);
    *(float4*)(ob + HW + r1) = o;

    o = make_float4(sGat[id[0] * 3 + 2], sGat[id[1] * 3 + 2],
                    sGat[id[2] * 3 + 2], sGat[id[3] * 3 + 2]);
    *(float4*)(ob + 2 * HW + r0) = o;
    o = make_float4(sGat[id[4] * 3 + 2], sGat[id[5] * 3 + 2],
                    sGat[id[6] * 3 + 2], sGat[id[7] * 3 + 2]);
    *(float4*)(ob + 2 * HW + r1) = o;
}

extern "C" void kernel_launch(void* const* d_in, const int* in_sizes, int n_in,
                              void* d_out, int out_size) {
    const float* x  = (const float*)d_in[0];
    const float* W1 = (const float*)d_in[1];
    const float* b1 = (const float*)d_in[2];
    const float* W2 = (const float*)d_in[3];
    const float* b2 = (const float*)d_in[4];
    float* out = (float*)d_out;

    dim3 grid(GRIDX, B_DIM);   // 128 x 32 = 4096 CTAs, 8 px/thread
    dim3 block(TPB);
    color_quant_kernel<<<grid, block>>>(x, W1, b1, W2, b2, out);
}